// round 9
// baseline (speedup 1.0000x reference)
#include <cuda_runtime.h>

// Problem constants (fixed by the dataset)
#define BB   64
#define NN   2048
#define EE   32768
#define DD   256
#define HH   256

#define SE      4                  // edge-pass blocks per batch
#define EPB     (EE / SE)          // 8192 edges per block
#define SPLIT_M 16                 // gather blocks per batch
#define MPB     (NN / SPLIT_M)     // 128 rows per gather block

// Scratch (__device__ globals, allocation-free; device-side refs only).
__device__ float g_wp[SE * BB * NN];         // w partials per edge-split
__device__ float g_up[SE * BB * NN];         // u partials per edge-split
__device__ float g_cp[SE * BB];              // c partials per edge-split
__device__ float g_s0p[SPLIT_M * BB * DD];   // S0 partials per gather-split
__device__ float g_v1[BB * HH];              // S1
__device__ float g_v2[BB * HH];              // pooled

// ---------------------------------------------------------------------------
// Kernel 1: w partials.  grid (BB, SE), 512 threads.
// ---------------------------------------------------------------------------
__global__ __launch_bounds__(512) void k_w(const int* __restrict__ adj_row,
                                           const int* __restrict__ adj_col,
                                           const float* __restrict__ adj_val,
                                           const int* __restrict__ curlen) {
    __shared__ float sw[NN];
    __shared__ float sc;
    int b   = blockIdx.x;
    int se  = blockIdx.y;
    int tid = threadIdx.x;

    for (int i = tid; i < NN; i += 512) sw[i] = 0.f;
    if (tid == 0) sc = 0.f;
    __syncthreads();

    int L = curlen ? *curlen : 512;
    size_t base = (size_t)b * EE + (size_t)se * EPB;
    const int4*   r4 = (const int4*)  (adj_row + base);
    const int4*   c4 = (const int4*)  (adj_col + base);
    const float4* v4 = (const float4*)(adj_val + base);
    const int NV = EPB / 4;

    float cpart = 0.f;
    for (int i = tid; i < NV; i += 512) {
        int4 r = r4[i]; int4 c = c4[i]; float4 v = v4[i];
        if (r.x < L) { atomicAdd(&sw[c.x], v.x); cpart += v.x; }
        if (r.y < L) { atomicAdd(&sw[c.y], v.y); cpart += v.y; }
        if (r.z < L) { atomicAdd(&sw[c.z], v.z); cpart += v.z; }
        if (r.w < L) { atomicAdd(&sw[c.w], v.w); cpart += v.w; }
    }
    #pragma unroll
    for (int off = 16; off > 0; off >>= 1)
        cpart += __shfl_down_sync(0xFFFFFFFFu, cpart, off);
    if ((tid & 31) == 0) atomicAdd(&sc, cpart);
    __syncthreads();

    float* dst = g_wp + ((size_t)se * BB + b) * NN;
    for (int i = tid; i < NN; i += 512) dst[i] = sw[i];
    if (tid == 0) g_cp[se * BB + b] = sc;
}

// ---------------------------------------------------------------------------
// Kernel 2: u partials.  grid (BB, SE), 512 threads.
// ---------------------------------------------------------------------------
__global__ __launch_bounds__(512) void k_u(const int* __restrict__ adj_row,
                                           const int* __restrict__ adj_col,
                                           const float* __restrict__ adj_val) {
    __shared__ float sw[NN];
    __shared__ float su[NN];
    int b   = blockIdx.x;
    int se  = blockIdx.y;
    int tid = threadIdx.x;

    for (int i = tid; i < NN; i += 512) {
        float w = 0.f;
        #pragma unroll
        for (int s = 0; s < SE; s++)
            w += g_wp[((size_t)s * BB + b) * NN + i];
        sw[i] = w;
        su[i] = 0.f;
    }
    __syncthreads();

    size_t base = (size_t)b * EE + (size_t)se * EPB;
    const int4*   r4 = (const int4*)  (adj_row + base);
    const int4*   c4 = (const int4*)  (adj_col + base);
    const float4* v4 = (const float4*)(adj_val + base);
    const int NV = EPB / 4;

    for (int i = tid; i < NV; i += 512) {
        int4 r = r4[i]; int4 c = c4[i]; float4 v = v4[i];
        atomicAdd(&su[c.x], v.x * sw[r.x]);
        atomicAdd(&su[c.y], v.y * sw[r.y]);
        atomicAdd(&su[c.z], v.z * sw[r.z]);
        atomicAdd(&su[c.w], v.w * sw[r.w]);
    }
    __syncthreads();

    float* dst = g_up + ((size_t)se * BB + b) * NN;
    for (int i = tid; i < NN; i += 512) dst[i] = su[i];
}

// ---------------------------------------------------------------------------
// Kernel 3: S0 partials. grid (BB, SPLIT_M), 512 threads.
// ---------------------------------------------------------------------------
__global__ __launch_bounds__(512) void k_s0(const int* __restrict__ neighbors,
                                            const float* __restrict__ emb) {
    __shared__ float  su[MPB];
    __shared__ int    snb[MPB];
    __shared__ float4 red[8][64];
    int b   = blockIdx.x;
    int tid = threadIdx.x;
    int m0  = blockIdx.y * MPB;

    if (tid < MPB) {
        float u = 0.f;
        #pragma unroll
        for (int s = 0; s < SE; s++)
            u += g_up[((size_t)s * BB + b) * NN + m0 + tid];
        su[tid]  = u;
        snb[tid] = neighbors[(size_t)b * NN + m0 + tid];
    }
    __syncthreads();

    int dg = tid & 63;
    int rg = tid >> 6;

    float4 acc = make_float4(0.f, 0.f, 0.f, 0.f);
    #pragma unroll
    for (int i = rg; i < MPB; i += 8) {
        float u = su[i];
        const float4* row = (const float4*)(emb + (size_t)snb[i] * DD);
        float4 e = __ldg(&row[dg]);
        acc.x += u * e.x;
        acc.y += u * e.y;
        acc.z += u * e.z;
        acc.w += u * e.w;
    }
    red[rg][dg] = acc;
    __syncthreads();

    if (tid < 64) {
        float4 s = make_float4(0.f, 0.f, 0.f, 0.f);
        #pragma unroll
        for (int r = 0; r < 8; r++) {
            float4 a = red[r][tid];
            s.x += a.x; s.y += a.y; s.z += a.z; s.w += a.w;
        }
        float4* dst = (float4*)(g_s0p + ((size_t)blockIdx.y * BB + b) * DD);
        dst[tid] = s;
    }
}

// ---------------------------------------------------------------------------
// Kernels 4-6: stage GEMM  C[64,256] = epi(A[64,256] @ W[256,256]).
// grid 32 = (rowg = bid>>3: 16 rows) x (colg = bid&7: 32 cols). 512 threads:
//   c4g = tid&7 (float4 col group), r = (tid>>3)&15 (local row), kh = tid>>7
//   (K quarter: 64 iters -> short serial LDG chain).
// A staged in smem (stride 260: conflict-free). W streamed from L2 (32KB
// slice per block -> per-SM weight bytes tiny). K-partials reduced in smem.
// MODE 1: A = sum of g_s0p partials (k_red folded here); C = g_v1; +c*b1.
// MODE 2: A = g_v1; C = g_v2; *invL + b2.
// MODE 3: A = g_v2; C = outp; relu(+fc1b).
// ---------------------------------------------------------------------------
template<int MODE>
__global__ __launch_bounds__(512) void k_gemm(
        const float* __restrict__ Wm,
        const float* __restrict__ bias,
        const int* __restrict__ curlen,
        float* __restrict__ outp) {
    __shared__ float  sA[16][260];
    __shared__ float4 sred[3][16][8];
    __shared__ float  scv[16];
    int rowg = blockIdx.x >> 3;   // 0..3
    int colg = blockIdx.x & 7;    // 0..7
    int tid  = threadIdx.x;
    int c4g  = tid & 7;
    int r    = (tid >> 3) & 15;
    int kh   = tid >> 7;          // 0..3

    // --- stage A slice (16 rows x 256) into smem ---
    #pragma unroll
    for (int k = 0; k < 2; k++) {
        int pos  = tid + k * 512;      // 0..1023
        int row  = pos >> 6;           // 0..15
        int d4   = pos & 63;
        int grow = rowg * 16 + row;
        float4 v;
        if (MODE == 1) {
            v = make_float4(0.f, 0.f, 0.f, 0.f);
            #pragma unroll
            for (int sm = 0; sm < SPLIT_M; sm++) {
                float4 p = __ldg((const float4*)(g_s0p +
                        ((size_t)sm * BB + grow) * DD) + d4);
                v.x += p.x; v.y += p.y; v.z += p.z; v.w += p.w;
            }
        } else {
            const float* A = (MODE == 2) ? g_v1 : g_v2;
            v = __ldg((const float4*)(A + (size_t)grow * HH) + d4);
        }
        sA[row][d4 * 4 + 0] = v.x;
        sA[row][d4 * 4 + 1] = v.y;
        sA[row][d4 * 4 + 2] = v.z;
        sA[row][d4 * 4 + 3] = v.w;
    }
    if (MODE == 1 && tid < 16) {
        float c = 0.f;
        #pragma unroll
        for (int s = 0; s < SE; s++) c += g_cp[s * BB + rowg * 16 + tid];
        scv[tid] = c;
    }
    __syncthreads();

    // --- K-quarter accumulation: 64 float4 weight loads per thread ---
    const float4* W4 = (const float4*)Wm;
    int cj = colg * 8 + c4g;           // float4 column index 0..63
    float4 acc = make_float4(0.f, 0.f, 0.f, 0.f);
    int d0 = kh * 64;
    #pragma unroll 16
    for (int j = 0; j < 64; j++) {
        int d = d0 + j;
        float  a = sA[r][d];
        float4 w = __ldg(&W4[(size_t)d * 64 + cj]);
        acc.x += a * w.x; acc.y += a * w.y;
        acc.z += a * w.z; acc.w += a * w.w;
    }

    if (kh > 0) sred[kh - 1][r][c4g] = acc;
    __syncthreads();

    if (kh == 0) {
        #pragma unroll
        for (int p = 0; p < 3; p++) {
            float4 t = sred[p][r][c4g];
            acc.x += t.x; acc.y += t.y; acc.z += t.z; acc.w += t.w;
        }
        float4 bb = __ldg((const float4*)bias + cj);
        if (MODE == 1) {
            float cv = scv[r];
            acc.x += cv * bb.x; acc.y += cv * bb.y;
            acc.z += cv * bb.z; acc.w += cv * bb.w;
        } else if (MODE == 2) {
            int L = curlen ? __ldg(curlen) : 512;
            float invL = 1.f / (float)L;
            acc.x = acc.x * invL + bb.x; acc.y = acc.y * invL + bb.y;
            acc.z = acc.z * invL + bb.z; acc.w = acc.w * invL + bb.w;
        } else {
            acc.x += bb.x; acc.y += bb.y; acc.z += bb.z; acc.w += bb.w;
            acc.x = acc.x > 0.f ? acc.x : 0.f;
            acc.y = acc.y > 0.f ? acc.y : 0.f;
            acc.z = acc.z > 0.f ? acc.z : 0.f;
            acc.w = acc.w > 0.f ? acc.w : 0.f;
        }
        float* C = (MODE == 1) ? g_v1 : (MODE == 2) ? g_v2 : outp;
        int grow = rowg * 16 + r;
        ((float4*)(C + (size_t)grow * HH))[cj] = acc;
    }
}

// ---------------------------------------------------------------------------
extern "C" void kernel_launch(void* const* d_in, const int* in_sizes, int n_in,
                              void* d_out, int out_size) {
    const int*   neighbors = (const int*)  d_in[0];
    const int*   adj_row   = (const int*)  d_in[1];
    const int*   adj_col   = (const int*)  d_in[2];
    const float* adj_val   = (const float*)d_in[3];
    const float* emb       = (const float*)d_in[4];
    const float* W1        = (const float*)d_in[5];
    const float* b1        = (const float*)d_in[6];
    const float* W2        = (const float*)d_in[7];
    const float* b2        = (const float*)d_in[8];
    const float* fc1w      = (const float*)d_in[9];
    const float* fc1b      = (const float*)d_in[10];
    const int*   curlen    = (n_in >= 12) ? (const int*)d_in[11] : nullptr;
    float*       out       = (float*)d_out;

    k_w  <<<dim3(BB, SE), 512>>>(adj_row, adj_col, adj_val, curlen);
    k_u  <<<dim3(BB, SE), 512>>>(adj_row, adj_col, adj_val);
    k_s0 <<<dim3(BB, SPLIT_M), 512>>>(neighbors, emb);
    k_gemm<1><<<32, 512>>>(W1,   b1,   curlen, nullptr);
    k_gemm<2><<<32, 512>>>(W2,   b2,   curlen, nullptr);
    k_gemm<3><<<32, 512>>>(fc1w, fc1b, curlen, out);
}

// round 10
// speedup vs baseline: 1.0820x; 1.0820x over previous
#include <cuda_runtime.h>

// Problem constants (fixed by the dataset)
#define BB   64
#define NN   2048
#define EE   32768
#define DD   256
#define HH   256

#define SE      4                  // edge-pass blocks per batch
#define EPB     (EE / SE)          // 8192 edges per block
#define SPLIT_M 16                 // gather blocks per batch
#define MPB     (NN / SPLIT_M)     // 128 rows per gather block

// Scratch (__device__ globals, allocation-free; device-side refs only).
__device__ float g_wp[SE * BB * NN];         // w partials per edge-split
__device__ float g_up[SE * BB * NN];         // u partials per edge-split
__device__ float g_cp[SE * BB];              // c partials per edge-split
__device__ float g_s0p[SPLIT_M * BB * DD];   // S0 partials per gather-split
__device__ float g_v1[BB * HH];              // S1
__device__ float g_v2[BB * HH];              // pooled

// ---------------------------------------------------------------------------
// Kernel 1: w partials.  grid (BB, SE)=256, 512 threads.  (R5, unchanged)
// ---------------------------------------------------------------------------
__global__ __launch_bounds__(512) void k_w(const int* __restrict__ adj_row,
                                           const int* __restrict__ adj_col,
                                           const float* __restrict__ adj_val,
                                           const int* __restrict__ curlen) {
    __shared__ float sw[NN];
    __shared__ float sc;
    int b   = blockIdx.x;
    int se  = blockIdx.y;
    int tid = threadIdx.x;

    for (int i = tid; i < NN; i += 512) sw[i] = 0.f;
    if (tid == 0) sc = 0.f;
    __syncthreads();

    int L = curlen ? *curlen : 512;
    size_t base = (size_t)b * EE + (size_t)se * EPB;
    const int4*   r4 = (const int4*)  (adj_row + base);
    const int4*   c4 = (const int4*)  (adj_col + base);
    const float4* v4 = (const float4*)(adj_val + base);
    const int NV = EPB / 4;

    float cpart = 0.f;
    for (int i = tid; i < NV; i += 512) {
        int4 r = r4[i]; int4 c = c4[i]; float4 v = v4[i];
        if (r.x < L) { atomicAdd(&sw[c.x], v.x); cpart += v.x; }
        if (r.y < L) { atomicAdd(&sw[c.y], v.y); cpart += v.y; }
        if (r.z < L) { atomicAdd(&sw[c.z], v.z); cpart += v.z; }
        if (r.w < L) { atomicAdd(&sw[c.w], v.w); cpart += v.w; }
    }
    #pragma unroll
    for (int off = 16; off > 0; off >>= 1)
        cpart += __shfl_down_sync(0xFFFFFFFFu, cpart, off);
    if ((tid & 31) == 0) atomicAdd(&sc, cpart);
    __syncthreads();

    float* dst = g_wp + ((size_t)se * BB + b) * NN;
    for (int i = tid; i < NN; i += 512) dst[i] = sw[i];
    if (tid == 0) g_cp[se * BB + b] = sc;
}

// ---------------------------------------------------------------------------
// Kernel 2: u partials.  grid (BB, SE)=256, 512 threads.  (R5, unchanged)
// ---------------------------------------------------------------------------
__global__ __launch_bounds__(512) void k_u(const int* __restrict__ adj_row,
                                           const int* __restrict__ adj_col,
                                           const float* __restrict__ adj_val) {
    __shared__ float sw[NN];
    __shared__ float su[NN];
    int b   = blockIdx.x;
    int se  = blockIdx.y;
    int tid = threadIdx.x;

    for (int i = tid; i < NN; i += 512) {
        float w = 0.f;
        #pragma unroll
        for (int s = 0; s < SE; s++)
            w += g_wp[((size_t)s * BB + b) * NN + i];
        sw[i] = w;
        su[i] = 0.f;
    }
    __syncthreads();

    size_t base = (size_t)b * EE + (size_t)se * EPB;
    const int4*   r4 = (const int4*)  (adj_row + base);
    const int4*   c4 = (const int4*)  (adj_col + base);
    const float4* v4 = (const float4*)(adj_val + base);
    const int NV = EPB / 4;

    for (int i = tid; i < NV; i += 512) {
        int4 r = r4[i]; int4 c = c4[i]; float4 v = v4[i];
        atomicAdd(&su[c.x], v.x * sw[r.x]);
        atomicAdd(&su[c.y], v.y * sw[r.y]);
        atomicAdd(&su[c.z], v.z * sw[r.z]);
        atomicAdd(&su[c.w], v.w * sw[r.w]);
    }
    __syncthreads();

    float* dst = g_up + ((size_t)se * BB + b) * NN;
    for (int i = tid; i < NN; i += 512) dst[i] = su[i];
}

// ---------------------------------------------------------------------------
// Kernel 3: S0 partials. grid (BB, SPLIT_M)=1024, 512 threads. (unchanged)
// ---------------------------------------------------------------------------
__global__ __launch_bounds__(512) void k_s0(const int* __restrict__ neighbors,
                                            const float* __restrict__ emb) {
    __shared__ float  su[MPB];
    __shared__ int    snb[MPB];
    __shared__ float4 red[8][64];
    int b   = blockIdx.x;
    int tid = threadIdx.x;
    int m0  = blockIdx.y * MPB;

    if (tid < MPB) {
        float u = 0.f;
        #pragma unroll
        for (int s = 0; s < SE; s++)
            u += g_up[((size_t)s * BB + b) * NN + m0 + tid];
        su[tid]  = u;
        snb[tid] = neighbors[(size_t)b * NN + m0 + tid];
    }
    __syncthreads();

    int dg = tid & 63;
    int rg = tid >> 6;

    float4 acc = make_float4(0.f, 0.f, 0.f, 0.f);
    #pragma unroll
    for (int i = rg; i < MPB; i += 8) {
        float u = su[i];
        const float4* row = (const float4*)(emb + (size_t)snb[i] * DD);
        float4 e = __ldg(&row[dg]);
        acc.x += u * e.x;
        acc.y += u * e.y;
        acc.z += u * e.z;
        acc.w += u * e.w;
    }
    red[rg][dg] = acc;
    __syncthreads();

    if (tid < 64) {
        float4 s = make_float4(0.f, 0.f, 0.f, 0.f);
        #pragma unroll
        for (int r = 0; r < 8; r++) {
            float4 a = red[r][tid];
            s.x += a.x; s.y += a.y; s.z += a.z; s.w += a.w;
        }
        float4* dst = (float4*)(g_s0p + ((size_t)blockIdx.y * BB + b) * DD);
        dst[tid] = s;
    }
}

// ---------------------------------------------------------------------------
// Kernels 4-6: matvec stage, GRID 256 (>=148: avoids the low-grid issue
// throttle seen on every grid<=64 chain variant). Block (b = bid>>2,
// cg = bid&3: output cols cg*64..+63), 256 threads = (c = tid&63) x
// (ks = tid>>6: K quarter of 64 iters). x vector staged in smem (broadcast
// reads); weight loads coalesced 128B/warp; K-partials reduced via smem.
// MODE 1: x = sum g_s0p partials; y = x@W1 + c*b1        -> g_v1
// MODE 2: x = g_v1;               y = (x@W2)*invL + b2   -> g_v2
// MODE 3: x = g_v2;               y = relu(x@fc1w+fc1b)  -> outp
// ---------------------------------------------------------------------------
template<int MODE>
__global__ __launch_bounds__(256) void k_mv(
        const float* __restrict__ Wm,
        const float* __restrict__ bias,
        const int* __restrict__ curlen,
        float* __restrict__ outp) {
    __shared__ float sx[DD];
    __shared__ float sred[3][64];
    __shared__ float scv;
    int b   = blockIdx.x >> 2;
    int cg  = blockIdx.x & 3;
    int tid = threadIdx.x;
    int c   = tid & 63;
    int ks  = tid >> 6;          // 0..3
    int col = cg * 64 + c;

    // stage x (256 elements; one per thread)
    if (MODE == 1) {
        float s0 = 0.f;
        #pragma unroll
        for (int sm = 0; sm < SPLIT_M; sm++)
            s0 += __ldg(&g_s0p[((size_t)sm * BB + b) * DD + tid]);
        sx[tid] = s0;
        if (tid == 0) {
            float cv = 0.f;
            #pragma unroll
            for (int s = 0; s < SE; s++) cv += g_cp[s * BB + b];
            scv = cv;
        }
    } else {
        const float* A = (MODE == 2) ? g_v1 : g_v2;
        sx[tid] = __ldg(&A[(size_t)b * HH + tid]);
    }
    __syncthreads();

    // K-quarter accumulation: 64 coalesced weight loads per thread
    float acc = 0.f;
    int k0 = ks * 64;
    #pragma unroll 16
    for (int j = 0; j < 64; j++) {
        int k = k0 + j;
        acc += sx[k] * __ldg(&Wm[(size_t)k * HH + col]);
    }

    if (ks > 0) sred[ks - 1][c] = acc;
    __syncthreads();

    if (ks == 0) {
        acc += sred[0][c] + sred[1][c] + sred[2][c];
        float bb = __ldg(&bias[col]);
        float y;
        if (MODE == 1) {
            y = acc + scv * bb;
        } else if (MODE == 2) {
            int L = curlen ? __ldg(curlen) : 512;
            y = acc * (1.f / (float)L) + bb;
        } else {
            y = acc + bb;
            y = y > 0.f ? y : 0.f;
        }
        float* C = (MODE == 1) ? g_v1 : (MODE == 2) ? g_v2 : outp;
        C[(size_t)b * HH + col] = y;
    }
}

// ---------------------------------------------------------------------------
extern "C" void kernel_launch(void* const* d_in, const int* in_sizes, int n_in,
                              void* d_out, int out_size) {
    const int*   neighbors = (const int*)  d_in[0];
    const int*   adj_row   = (const int*)  d_in[1];
    const int*   adj_col   = (const int*)  d_in[2];
    const float* adj_val   = (const float*)d_in[3];
    const float* emb       = (const float*)d_in[4];
    const float* W1        = (const float*)d_in[5];
    const float* b1        = (const float*)d_in[6];
    const float* W2        = (const float*)d_in[7];
    const float* b2        = (const float*)d_in[8];
    const float* fc1w      = (const float*)d_in[9];
    const float* fc1b      = (const float*)d_in[10];
    const int*   curlen    = (n_in >= 12) ? (const int*)d_in[11] : nullptr;
    float*       out       = (float*)d_out;

    k_w  <<<dim3(BB, SE), 512>>>(adj_row, adj_col, adj_val, curlen);
    k_u  <<<dim3(BB, SE), 512>>>(adj_row, adj_col, adj_val);
    k_s0 <<<dim3(BB, SPLIT_M), 512>>>(neighbors, emb);
    k_mv<1><<<BB * 4, 256>>>(W1,   b1,   curlen, nullptr);
    k_mv<2><<<BB * 4, 256>>>(W2,   b2,   curlen, nullptr);
    k_mv<3><<<BB * 4, 256>>>(fc1w, fc1b, curlen, out);
}

// round 11
// speedup vs baseline: 1.4372x; 1.3282x over previous
#include <cuda_runtime.h>

// Problem constants (fixed by the dataset)
#define BB   64
#define NN   2048
#define EE   32768
#define DD   256
#define HH   256

#define SE      4                  // edge-split per batch
#define EPB     (EE / SE)          // 8192 edges per item
#define SPLIT_M 16                 // gather items per batch
#define MPB     (NN / SPLIT_M)     // 128 rows per gather item

#define NBLK    148                // one block per SM -> guaranteed resident

// Scratch (__device__ globals, allocation-free; device-side refs only).
__device__ float g_wp[SE * BB * NN];
__device__ float g_up[SE * BB * NN];
__device__ float g_cp[SE * BB];
__device__ float g_s0p[SPLIT_M * BB * DD];

// Grid-barrier state (zero-initialized; invariants maintained across replays:
// cnt returns to 0 after each barrier, flag toggles -> sense read pre-arrival).
__device__ int g_cnt[3];
__device__ int g_flag[3];

// Sense-reversing grid barrier. Safe across graph replays: each block reads
// the current flag BEFORE incrementing (flip can only happen after ALL blocks
// incremented, so the read is strictly pre-flip); last arriver resets cnt,
// fences, then flips the flag.
__device__ __forceinline__ void gbar(int i) {
    __syncthreads();
    if (threadIdx.x == 0) {
        __threadfence();
        volatile int* vf = (volatile int*)&g_flag[i];
        int sense = *vf;
        int prev = atomicAdd(&g_cnt[i], 1);
        if (prev == NBLK - 1) {
            g_cnt[i] = 0;
            __threadfence();
            atomicExch(&g_flag[i], sense ^ 1);
        } else {
            while (*vf == sense) __nanosleep(64);
        }
        __threadfence();
    }
    __syncthreads();
}

// Shared-memory union across phases (~18.5 KB max).
union SmemU {
    struct { float sw[NN]; float sc; } w;
    struct { float sw[NN]; float su[NN]; } u;
    struct { float su[MPB]; int snb[MPB]; float4 red[16][64]; } s0;
    struct { float sx[DD]; float sy[HH]; float4 red[16][64]; float sc; } ch;
};

__global__ __launch_bounds__(1024, 1) void k_all(
        const int* __restrict__ neighbors,
        const int* __restrict__ adj_row,
        const int* __restrict__ adj_col,
        const float* __restrict__ adj_val,
        const float* __restrict__ emb,
        const float* __restrict__ W1,   const float* __restrict__ b1,
        const float* __restrict__ W2,   const float* __restrict__ b2,
        const float* __restrict__ fc1w, const float* __restrict__ fc1b,
        const int* __restrict__ curlen,
        float* __restrict__ out) {
    __shared__ SmemU sm;
    int bid = blockIdx.x;
    int tid = threadIdx.x;
    int L = curlen ? __ldg(curlen) : 512;

    // ============ Phase 1: w partials (items = (b, se), 256 total) ============
    for (int it = bid; it < BB * SE; it += NBLK) {
        int b  = it >> 2;
        int se = it & 3;

        for (int i = tid; i < NN; i += 1024) sm.w.sw[i] = 0.f;
        if (tid == 0) sm.w.sc = 0.f;
        __syncthreads();

        size_t base = (size_t)b * EE + (size_t)se * EPB;
        const int4*   r4 = (const int4*)  (adj_row + base);
        const int4*   c4 = (const int4*)  (adj_col + base);
        const float4* v4 = (const float4*)(adj_val + base);
        const int NV = EPB / 4;  // 2048

        float cpart = 0.f;
        for (int i = tid; i < NV; i += 1024) {
            int4 r = r4[i]; int4 c = c4[i]; float4 v = v4[i];
            if (r.x < L) { atomicAdd(&sm.w.sw[c.x], v.x); cpart += v.x; }
            if (r.y < L) { atomicAdd(&sm.w.sw[c.y], v.y); cpart += v.y; }
            if (r.z < L) { atomicAdd(&sm.w.sw[c.z], v.z); cpart += v.z; }
            if (r.w < L) { atomicAdd(&sm.w.sw[c.w], v.w); cpart += v.w; }
        }
        #pragma unroll
        for (int off = 16; off > 0; off >>= 1)
            cpart += __shfl_down_sync(0xFFFFFFFFu, cpart, off);
        if ((tid & 31) == 0) atomicAdd(&sm.w.sc, cpart);
        __syncthreads();

        float* dst = g_wp + ((size_t)se * BB + b) * NN;
        for (int i = tid; i < NN; i += 1024) dst[i] = sm.w.sw[i];
        if (tid == 0) g_cp[se * BB + b] = sm.w.sc;
        __syncthreads();
    }
    gbar(0);

    // ============ Phase 2: u partials (items = (b, se), 256 total) ============
    for (int it = bid; it < BB * SE; it += NBLK) {
        int b  = it >> 2;
        int se = it & 3;

        for (int i = tid; i < NN; i += 1024) {
            float w = 0.f;
            #pragma unroll
            for (int s = 0; s < SE; s++)
                w += g_wp[((size_t)s * BB + b) * NN + i];
            sm.u.sw[i] = w;
            sm.u.su[i] = 0.f;
        }
        __syncthreads();

        size_t base = (size_t)b * EE + (size_t)se * EPB;
        const int4*   r4 = (const int4*)  (adj_row + base);
        const int4*   c4 = (const int4*)  (adj_col + base);
        const float4* v4 = (const float4*)(adj_val + base);
        const int NV = EPB / 4;

        for (int i = tid; i < NV; i += 1024) {
            int4 r = r4[i]; int4 c = c4[i]; float4 v = v4[i];
            atomicAdd(&sm.u.su[c.x], v.x * sm.u.sw[r.x]);
            atomicAdd(&sm.u.su[c.y], v.y * sm.u.sw[r.y]);
            atomicAdd(&sm.u.su[c.z], v.z * sm.u.sw[r.z]);
            atomicAdd(&sm.u.su[c.w], v.w * sm.u.sw[r.w]);
        }
        __syncthreads();

        float* dst = g_up + ((size_t)se * BB + b) * NN;
        for (int i = tid; i < NN; i += 1024) dst[i] = sm.u.su[i];
        __syncthreads();
    }
    gbar(1);

    // ============ Phase 3: S0 partials (items = (b, mchunk), 1024 total) =====
    for (int it = bid; it < BB * SPLIT_M; it += NBLK) {
        int b  = it >> 4;
        int mc = it & 15;
        int m0 = mc * MPB;

        if (tid < MPB) {
            float u = 0.f;
            #pragma unroll
            for (int s = 0; s < SE; s++)
                u += g_up[((size_t)s * BB + b) * NN + m0 + tid];
            sm.s0.su[tid]  = u;
            sm.s0.snb[tid] = neighbors[(size_t)b * NN + m0 + tid];
        }
        __syncthreads();

        int dg = tid & 63;
        int rg = tid >> 6;   // 0..15

        float4 acc = make_float4(0.f, 0.f, 0.f, 0.f);
        #pragma unroll
        for (int i = rg; i < MPB; i += 16) {
            float u = sm.s0.su[i];
            const float4* row = (const float4*)(emb + (size_t)sm.s0.snb[i] * DD);
            float4 e = __ldg(&row[dg]);
            acc.x += u * e.x;
            acc.y += u * e.y;
            acc.z += u * e.z;
            acc.w += u * e.w;
        }
        sm.s0.red[rg][dg] = acc;
        __syncthreads();

        if (tid < 64) {
            float4 s = make_float4(0.f, 0.f, 0.f, 0.f);
            #pragma unroll
            for (int r = 0; r < 16; r++) {
                float4 a = sm.s0.red[r][tid];
                s.x += a.x; s.y += a.y; s.z += a.z; s.w += a.w;
            }
            float4* dst = (float4*)(g_s0p + ((size_t)mc * BB + b) * DD);
            dst[tid] = s;
        }
        __syncthreads();
    }
    gbar(2);

    // ============ Phase 4: fused 3-matvec chain (items = batch, 64) ==========
    if (bid < BB) {
        int b  = bid;
        int hq = tid & 63;
        int q  = tid >> 6;   // 0..15

        if (tid < HH) {
            float s0 = 0.f;
            #pragma unroll
            for (int smi = 0; smi < SPLIT_M; smi++)
                s0 += g_s0p[((size_t)smi * BB + b) * DD + tid];
            sm.ch.sx[tid] = s0;
        } else if (tid == HH) {
            float c = 0.f;
            #pragma unroll
            for (int s = 0; s < SE; s++) c += g_cp[s * BB + b];
            sm.ch.sc = c;
        }
        __syncthreads();

        // ---- stage 1: sy = sx @ W1 + sc*b1 ----
        {
            const float4* W4 = (const float4*)W1;
            float4 acc = make_float4(0.f, 0.f, 0.f, 0.f);
            #pragma unroll
            for (int j = 0; j < 16; j++) {
                int d = q * 16 + j;
                float xv = sm.ch.sx[d];
                float4 wv = __ldg(&W4[(size_t)d * 64 + hq]);
                acc.x += xv * wv.x; acc.y += xv * wv.y;
                acc.z += xv * wv.z; acc.w += xv * wv.w;
            }
            sm.ch.red[q][hq] = acc;
            __syncthreads();
            if (tid < 64) {
                float4 s = make_float4(0.f, 0.f, 0.f, 0.f);
                #pragma unroll
                for (int r = 0; r < 16; r++) {
                    float4 a = sm.ch.red[r][tid];
                    s.x += a.x; s.y += a.y; s.z += a.z; s.w += a.w;
                }
                float4 bb = ((const float4*)b1)[tid];
                float  c  = sm.ch.sc;
                s.x += c * bb.x; s.y += c * bb.y;
                s.z += c * bb.z; s.w += c * bb.w;
                ((float4*)sm.ch.sy)[tid] = s;
            }
            __syncthreads();
        }

        // ---- stage 2: sx = (sy @ W2) / L + b2 ----
        {
            const float4* W4 = (const float4*)W2;
            float4 acc = make_float4(0.f, 0.f, 0.f, 0.f);
            #pragma unroll
            for (int j = 0; j < 16; j++) {
                int d = q * 16 + j;
                float xv = sm.ch.sy[d];
                float4 wv = __ldg(&W4[(size_t)d * 64 + hq]);
                acc.x += xv * wv.x; acc.y += xv * wv.y;
                acc.z += xv * wv.z; acc.w += xv * wv.w;
            }
            sm.ch.red[q][hq] = acc;
            __syncthreads();
            if (tid < 64) {
                float4 s = make_float4(0.f, 0.f, 0.f, 0.f);
                #pragma unroll
                for (int r = 0; r < 16; r++) {
                    float4 a = sm.ch.red[r][tid];
                    s.x += a.x; s.y += a.y; s.z += a.z; s.w += a.w;
                }
                float invL = 1.f / (float)L;
                float4 bb = ((const float4*)b2)[tid];
                s.x = s.x * invL + bb.x; s.y = s.y * invL + bb.y;
                s.z = s.z * invL + bb.z; s.w = s.w * invL + bb.w;
                ((float4*)sm.ch.sx)[tid] = s;
            }
            __syncthreads();
        }

        // ---- stage 3: out = relu(sx @ fc1w + fc1b) ----
        {
            const float4* W4 = (const float4*)fc1w;
            float4 acc = make_float4(0.f, 0.f, 0.f, 0.f);
            #pragma unroll
            for (int j = 0; j < 16; j++) {
                int d = q * 16 + j;
                float xv = sm.ch.sx[d];
                float4 wv = __ldg(&W4[(size_t)d * 64 + hq]);
                acc.x += xv * wv.x; acc.y += xv * wv.y;
                acc.z += xv * wv.z; acc.w += xv * wv.w;
            }
            sm.ch.red[q][hq] = acc;
            __syncthreads();
            if (tid < 64) {
                float4 s = make_float4(0.f, 0.f, 0.f, 0.f);
                #pragma unroll
                for (int r = 0; r < 16; r++) {
                    float4 a = sm.ch.red[r][tid];
                    s.x += a.x; s.y += a.y; s.z += a.z; s.w += a.w;
                }
                float4 bb = ((const float4*)fc1b)[tid];
                s.x += bb.x; s.y += bb.y; s.z += bb.z; s.w += bb.w;
                s.x = s.x > 0.f ? s.x : 0.f;
                s.y = s.y > 0.f ? s.y : 0.f;
                s.z = s.z > 0.f ? s.z : 0.f;
                s.w = s.w > 0.f ? s.w : 0.f;
                ((float4*)(out + (size_t)b * HH))[tid] = s;
            }
        }
    }
}

// ---------------------------------------------------------------------------
extern "C" void kernel_launch(void* const* d_in, const int* in_sizes, int n_in,
                              void* d_out, int out_size) {
    const int*   neighbors = (const int*)  d_in[0];
    const int*   adj_row   = (const int*)  d_in[1];
    const int*   adj_col   = (const int*)  d_in[2];
    const float* adj_val   = (const float*)d_in[3];
    const float* emb       = (const float*)d_in[4];
    const float* W1        = (const float*)d_in[5];
    const float* b1        = (const float*)d_in[6];
    const float* W2        = (const float*)d_in[7];
    const float* b2        = (const float*)d_in[8];
    const float* fc1w      = (const float*)d_in[9];
    const float* fc1b      = (const float*)d_in[10];
    const int*   curlen    = (n_in >= 12) ? (const int*)d_in[11] : nullptr;
    float*       out       = (float*)d_out;

    k_all<<<NBLK, 1024>>>(neighbors, adj_row, adj_col, adj_val, emb,
                          W1, b1, W2, b2, fc1w, fc1b, curlen, out);
}

// round 12
// speedup vs baseline: 1.6497x; 1.1479x over previous
#include <cuda_runtime.h>

// Problem constants (fixed by the dataset)
#define BB   64
#define NN   2048
#define EE   32768
#define DD   256
#define HH   256

#define SE      4                  // edge-pass blocks per batch
#define EPB     (EE / SE)          // 8192 edges per block
#define SPLIT_M 16                 // gather blocks per batch
#define MPB     (NN / SPLIT_M)     // 128 rows per gather block

#define CNB     128                // chain kernel grid (1 block/SM, co-resident)

// Scratch (__device__ globals, allocation-free; device-side refs only).
__device__ float g_wp[SE * BB * NN];
__device__ float g_up[SE * BB * NN];
__device__ float g_cp[SE * BB];
__device__ float g_s0p[SPLIT_M * BB * DD];
__device__ float g_v1[BB * HH];
__device__ float g_v2[BB * HH];

// Chain grid-barrier state (R11-proven pattern; invariants hold across graph
// replays: cnt returns to 0, flag toggles, sense read strictly pre-flip).
__device__ int g2_cnt[2];
__device__ int g2_flag[2];

__device__ __forceinline__ void gbar2(int i) {
    __syncthreads();
    if (threadIdx.x == 0) {
        __threadfence();
        volatile int* vf = (volatile int*)&g2_flag[i];
        int sense = *vf;
        int prev = atomicAdd(&g2_cnt[i], 1);
        if (prev == CNB - 1) {
            g2_cnt[i] = 0;
            __threadfence();
            atomicExch(&g2_flag[i], sense ^ 1);
        } else {
            while (*vf == sense) __nanosleep(64);
        }
        __threadfence();
    }
    __syncthreads();
}

// ---------------------------------------------------------------------------
// Kernel 1: w partials.  grid (BB, SE)=256, 512 threads.  (R5, unchanged)
// ---------------------------------------------------------------------------
__global__ __launch_bounds__(512) void k_w(const int* __restrict__ adj_row,
                                           const int* __restrict__ adj_col,
                                           const float* __restrict__ adj_val,
                                           const int* __restrict__ curlen) {
    __shared__ float sw[NN];
    __shared__ float sc;
    int b   = blockIdx.x;
    int se  = blockIdx.y;
    int tid = threadIdx.x;

    for (int i = tid; i < NN; i += 512) sw[i] = 0.f;
    if (tid == 0) sc = 0.f;
    __syncthreads();

    int L = curlen ? *curlen : 512;
    size_t base = (size_t)b * EE + (size_t)se * EPB;
    const int4*   r4 = (const int4*)  (adj_row + base);
    const int4*   c4 = (const int4*)  (adj_col + base);
    const float4* v4 = (const float4*)(adj_val + base);
    const int NV = EPB / 4;

    float cpart = 0.f;
    for (int i = tid; i < NV; i += 512) {
        int4 r = r4[i]; int4 c = c4[i]; float4 v = v4[i];
        if (r.x < L) { atomicAdd(&sw[c.x], v.x); cpart += v.x; }
        if (r.y < L) { atomicAdd(&sw[c.y], v.y); cpart += v.y; }
        if (r.z < L) { atomicAdd(&sw[c.z], v.z); cpart += v.z; }
        if (r.w < L) { atomicAdd(&sw[c.w], v.w); cpart += v.w; }
    }
    #pragma unroll
    for (int off = 16; off > 0; off >>= 1)
        cpart += __shfl_down_sync(0xFFFFFFFFu, cpart, off);
    if ((tid & 31) == 0) atomicAdd(&sc, cpart);
    __syncthreads();

    float* dst = g_wp + ((size_t)se * BB + b) * NN;
    for (int i = tid; i < NN; i += 512) dst[i] = sw[i];
    if (tid == 0) g_cp[se * BB + b] = sc;
}

// ---------------------------------------------------------------------------
// Kernel 2: u partials.  grid (BB, SE)=256, 512 threads.  (R5, unchanged)
// ---------------------------------------------------------------------------
__global__ __launch_bounds__(512) void k_u(const int* __restrict__ adj_row,
                                           const int* __restrict__ adj_col,
                                           const float* __restrict__ adj_val) {
    __shared__ float sw[NN];
    __shared__ float su[NN];
    int b   = blockIdx.x;
    int se  = blockIdx.y;
    int tid = threadIdx.x;

    for (int i = tid; i < NN; i += 512) {
        float w = 0.f;
        #pragma unroll
        for (int s = 0; s < SE; s++)
            w += g_wp[((size_t)s * BB + b) * NN + i];
        sw[i] = w;
        su[i] = 0.f;
    }
    __syncthreads();

    size_t base = (size_t)b * EE + (size_t)se * EPB;
    const int4*   r4 = (const int4*)  (adj_row + base);
    const int4*   c4 = (const int4*)  (adj_col + base);
    const float4* v4 = (const float4*)(adj_val + base);
    const int NV = EPB / 4;

    for (int i = tid; i < NV; i += 512) {
        int4 r = r4[i]; int4 c = c4[i]; float4 v = v4[i];
        atomicAdd(&su[c.x], v.x * sw[r.x]);
        atomicAdd(&su[c.y], v.y * sw[r.y]);
        atomicAdd(&su[c.z], v.z * sw[r.z]);
        atomicAdd(&su[c.w], v.w * sw[r.w]);
    }
    __syncthreads();

    float* dst = g_up + ((size_t)se * BB + b) * NN;
    for (int i = tid; i < NN; i += 512) dst[i] = su[i];
}

// ---------------------------------------------------------------------------
// Kernel 3: S0 partials. grid (BB, SPLIT_M)=1024, 512 threads. (unchanged)
// ---------------------------------------------------------------------------
__global__ __launch_bounds__(512) void k_s0(const int* __restrict__ neighbors,
                                            const float* __restrict__ emb) {
    __shared__ float  su[MPB];
    __shared__ int    snb[MPB];
    __shared__ float4 red[8][64];
    int b   = blockIdx.x;
    int tid = threadIdx.x;
    int m0  = blockIdx.y * MPB;

    if (tid < MPB) {
        float u = 0.f;
        #pragma unroll
        for (int s = 0; s < SE; s++)
            u += g_up[((size_t)s * BB + b) * NN + m0 + tid];
        su[tid]  = u;
        snb[tid] = neighbors[(size_t)b * NN + m0 + tid];
    }
    __syncthreads();

    int dg = tid & 63;
    int rg = tid >> 6;

    float4 acc = make_float4(0.f, 0.f, 0.f, 0.f);
    #pragma unroll
    for (int i = rg; i < MPB; i += 8) {
        float u = su[i];
        const float4* row = (const float4*)(emb + (size_t)snb[i] * DD);
        float4 e = __ldg(&row[dg]);
        acc.x += u * e.x;
        acc.y += u * e.y;
        acc.z += u * e.z;
        acc.w += u * e.w;
    }
    red[rg][dg] = acc;
    __syncthreads();

    if (tid < 64) {
        float4 s = make_float4(0.f, 0.f, 0.f, 0.f);
        #pragma unroll
        for (int r = 0; r < 8; r++) {
            float4 a = red[r][tid];
            s.x += a.x; s.y += a.y; s.z += a.z; s.w += a.w;
        }
        float4* dst = (float4*)(g_s0p + ((size_t)blockIdx.y * BB + b) * DD);
        dst[tid] = s;
    }
}

// ---------------------------------------------------------------------------
// Kernel 4: persistent chain, grid CNB=128 (co-resident), 1024 threads.
// Stage item per block: 4 batches (bg = bid>>3) x 32 cols (cg = bid&7).
// Weight slice per block per stage = 32KB -> 4MB/stage chip traffic with 128
// active SMs of L2 BW (vs R5: 16MB over 64 SMs). Stages separated by gbar2
// since each v-row is produced by 8 different col-blocks.
// Thread: h = tid&31 (col), ks = tid>>5 (0..31, 8 k's each). W loads are
// warp-coalesced (lanes = consecutive h). A broadcast from smem.
// ---------------------------------------------------------------------------
__global__ __launch_bounds__(1024, 1) void k_chainp(
        const float* __restrict__ W1,   const float* __restrict__ b1,
        const float* __restrict__ W2,   const float* __restrict__ b2,
        const float* __restrict__ fc1w, const float* __restrict__ fc1b,
        const int* __restrict__ curlen,
        float* __restrict__ out) {
    __shared__ float sA[4][260];          // 4 batches x 256 (padded)
    __shared__ float sred[32][32][4];     // [ks][h][bb]
    __shared__ float scv[4];
    int bid = blockIdx.x;
    int tid = threadIdx.x;
    int bg  = bid >> 3;                   // 0..15
    int cg  = bid & 7;                    // 0..7
    int b0  = bg * 4;
    int h   = tid & 31;
    int ks  = tid >> 5;                   // 0..31
    int col = cg * 32 + h;
    int L = curlen ? __ldg(curlen) : 512;
    float invL = 1.f / (float)L;

    // ---- stage 1 A: reduce S0 partials for 4 batches; c partials ----
    {
        int bb = tid >> 8;                // 0..3
        int hh = tid & 255;
        float s0 = 0.f;
        #pragma unroll
        for (int sm = 0; sm < SPLIT_M; sm++)
            s0 += __ldg(&g_s0p[((size_t)sm * BB + b0 + bb) * DD + hh]);
        sA[bb][hh] = s0;
        if (tid < 4) {
            float c = 0.f;
            #pragma unroll
            for (int s = 0; s < SE; s++) c += g_cp[s * BB + b0 + tid];
            scv[tid] = c;
        }
    }
    __syncthreads();

    // ---- stage 1 compute: v1 = S0 @ W1 + c*b1 ----
    {
        float a0 = 0.f, a1 = 0.f, a2 = 0.f, a3 = 0.f;
        #pragma unroll
        for (int j = 0; j < 8; j++) {
            int k = ks * 8 + j;
            float w = __ldg(&W1[(size_t)k * HH + col]);
            a0 += sA[0][k] * w; a1 += sA[1][k] * w;
            a2 += sA[2][k] * w; a3 += sA[3][k] * w;
        }
        sred[ks][h][0] = a0; sred[ks][h][1] = a1;
        sred[ks][h][2] = a2; sred[ks][h][3] = a3;
        __syncthreads();
        if (tid < 128) {
            int bb = tid >> 5, hh = tid & 31;
            float s = 0.f;
            #pragma unroll
            for (int k2 = 0; k2 < 32; k2++) s += sred[k2][hh][bb];
            s += scv[bb] * __ldg(&b1[cg * 32 + hh]);
            g_v1[(size_t)(b0 + bb) * HH + cg * 32 + hh] = s;
        }
    }
    gbar2(0);

    // ---- stage 2 A: full v1 rows ----
    {
        int bb = tid >> 8, hh = tid & 255;
        sA[bb][hh] = g_v1[(size_t)(b0 + bb) * HH + hh];
    }
    __syncthreads();

    // ---- stage 2 compute: v2 = (v1 @ W2)*invL + b2 ----
    {
        float a0 = 0.f, a1 = 0.f, a2 = 0.f, a3 = 0.f;
        #pragma unroll
        for (int j = 0; j < 8; j++) {
            int k = ks * 8 + j;
            float w = __ldg(&W2[(size_t)k * HH + col]);
            a0 += sA[0][k] * w; a1 += sA[1][k] * w;
            a2 += sA[2][k] * w; a3 += sA[3][k] * w;
        }
        sred[ks][h][0] = a0; sred[ks][h][1] = a1;
        sred[ks][h][2] = a2; sred[ks][h][3] = a3;
        __syncthreads();
        if (tid < 128) {
            int bb = tid >> 5, hh = tid & 31;
            float s = 0.f;
            #pragma unroll
            for (int k2 = 0; k2 < 32; k2++) s += sred[k2][hh][bb];
            s = s * invL + __ldg(&b2[cg * 32 + hh]);
            g_v2[(size_t)(b0 + bb) * HH + cg * 32 + hh] = s;
        }
    }
    gbar2(1);

    // ---- stage 3 A: full v2 rows ----
    {
        int bb = tid >> 8, hh = tid & 255;
        sA[bb][hh] = g_v2[(size_t)(b0 + bb) * HH + hh];
    }
    __syncthreads();

    // ---- stage 3 compute: out = relu(v2 @ fc1w + fc1b) ----
    {
        float a0 = 0.f, a1 = 0.f, a2 = 0.f, a3 = 0.f;
        #pragma unroll
        for (int j = 0; j < 8; j++) {
            int k = ks * 8 + j;
            float w = __ldg(&fc1w[(size_t)k * HH + col]);
            a0 += sA[0][k] * w; a1 += sA[1][k] * w;
            a2 += sA[2][k] * w; a3 += sA[3][k] * w;
        }
        sred[ks][h][0] = a0; sred[ks][h][1] = a1;
        sred[ks][h][2] = a2; sred[ks][h][3] = a3;
        __syncthreads();
        if (tid < 128) {
            int bb = tid >> 5, hh = tid & 31;
            float s = 0.f;
            #pragma unroll
            for (int k2 = 0; k2 < 32; k2++) s += sred[k2][hh][bb];
            s += __ldg(&fc1b[cg * 32 + hh]);
            s = s > 0.f ? s : 0.f;
            out[(size_t)(b0 + bb) * HH + cg * 32 + hh] = s;
        }
    }
}

// ---------------------------------------------------------------------------
extern "C" void kernel_launch(void* const* d_in, const int* in_sizes, int n_in,
                              void* d_out, int out_size) {
    const int*   neighbors = (const int*)  d_in[0];
    const int*   adj_row   = (const int*)  d_in[1];
    const int*   adj_col   = (const int*)  d_in[2];
    const float* adj_val   = (const float*)d_in[3];
    const float* emb       = (const float*)d_in[4];
    const float* W1        = (const float*)d_in[5];
    const float* b1        = (const float*)d_in[6];
    const float* W2        = (const float*)d_in[7];
    const float* b2        = (const float*)d_in[8];
    const float* fc1w      = (const float*)d_in[9];
    const float* fc1b      = (const float*)d_in[10];
    const int*   curlen    = (n_in >= 12) ? (const int*)d_in[11] : nullptr;
    float*       out       = (float*)d_out;

    k_w     <<<dim3(BB, SE), 512>>>(adj_row, adj_col, adj_val, curlen);
    k_u     <<<dim3(BB, SE), 512>>>(adj_row, adj_col, adj_val);
    k_s0    <<<dim3(BB, SPLIT_M), 512>>>(neighbors, emb);
    k_chainp<<<CNB, 1024>>>(W1, b1, W2, b2, fc1w, fc1b, curlen, out);
}